// round 4
// baseline (speedup 1.0000x reference)
#include <cuda_runtime.h>
#include <cstddef>

// KitNET_5257039970983 — R4: vectorized LDS.128 everywhere, 112B pair stride.
// Inputs: x(B,100) f32, Wt(10,7,10), hbias_t(10,7), vbias_t(10,10),
//         Wh(7,10), hbias_h(7), vbias_h(10), clusters(10,10) i32
// Output: head_out(B,10) then tails(B,10), fp32.

#define NTILES 10
#define CDIM   10
#define HDIM   7
#define FDIM   100
#define TPB    256
#define RPB    512            // rows per block; thread packs rows (tid, tid+256)
#define XSTR   14             // u64 stride per pair-row: 112B -> 16B-aligned, conflict-free LDS.128

// ---- smem layout (byte offsets, 16B aligned) ----
#define OFF_X0    0                       // u64[256][14] = 28672
#define OFF_X1    28672                   // u64[256][14] = 28672
#define OFF_MT    57344                   // u64[10][10][10] = 8000  M_t[t][co][ci] packed (m,m)
#define OFF_BT    65344                   // u64[10][10]     = 800
#define OFF_MH    66144                   // u64[10][10]     = 800   MH[j][i]
#define OFF_BH    66944                   // u64[10]         = 80
#define OFF_PERM  67024                   // int[100]        = 400
#define OFF_TBASE 67424                   // int[10]         = 40
#define SMEM_BYTES 67488

typedef unsigned long long u64;

__device__ __forceinline__ u64 fma2(u64 a, u64 b, u64 c) {
    u64 d;
    asm("fma.rn.f32x2 %0, %1, %2, %3;" : "=l"(d) : "l"(a), "l"(b), "l"(c));
    return d;
}
__device__ __forceinline__ u64 pack2(float x, float y) {
    u64 d;
    asm("mov.b64 %0, {%1, %2};" : "=l"(d) : "f"(x), "f"(y));
    return d;
}
__device__ __forceinline__ void unpack2(u64 a, float& x, float& y) {
    asm("mov.b64 {%0, %1}, %2;" : "=f"(x), "=f"(y) : "l"(a));
}

// stage 10 gathered columns of one tile into the interleaved pair buffer
__device__ __forceinline__ void stage_tile(const float* __restrict__ xg,
                                           u64* __restrict__ xbu,
                                           const int* __restrict__ pp,
                                           int tbase, int nrows, int tid)
{
    const int npairs = min(nrows, 256);
    if (tbase >= 0) {
        // contiguous even base: 2x LDG.64 + 1x STS.128 per item
        const int ntot = npairs * 5;
        #pragma unroll 2
        for (int i = tid; i < ntot; i += TPB) {
            unsigned p = (unsigned)i / 5u;
            unsigned k = (unsigned)i - p * 5u;
            const float* g0 = xg + p * FDIM + (unsigned)tbase + 2u * k;
            float2 v0 = *(const float2*)g0;
            float2 v1 = make_float2(0.0f, 0.0f);
            if ((int)p + 256 < nrows) v1 = *(const float2*)(g0 + 256 * FDIM);
            float4 q = make_float4(v0.x, v1.x, v0.y, v1.y);
            *(float4*)(xbu + p * XSTR + 2u * k) = q;
        }
    } else {
        // generic gather: 2x LDG.32 + 1x STS.64 per item
        const int ntot = npairs * 10;
        #pragma unroll 2
        for (int i = tid; i < ntot; i += TPB) {
            unsigned p = (unsigned)i / 10u;
            unsigned j = (unsigned)i - p * 10u;
            unsigned col = (unsigned)pp[j];
            float v0 = xg[p * FDIM + col];
            float v1 = 0.0f;
            if ((int)p + 256 < nrows) v1 = xg[(p + 256u) * FDIM + col];
            xbu[p * XSTR + j] = pack2(v0, v1);
        }
    }
}

// err = xc @ M_t + b_t ; return packed sum of squares over outputs
__device__ __forceinline__ u64 compute_tile(const u64* __restrict__ xrow,
                                            const u64* __restrict__ Mt,
                                            const u64* __restrict__ bt)
{
    const ulonglong2* xv = (const ulonglong2*)xrow;   // 16B aligned (XSTR even)
    u64 xc[CDIM];
    #pragma unroll
    for (int cc = 0; cc < 5; ++cc) {
        ulonglong2 v = xv[cc];
        xc[2*cc]   = v.x;
        xc[2*cc+1] = v.y;
    }
    const ulonglong2* Mv  = (const ulonglong2*)Mt;
    const ulonglong2* btv = (const ulonglong2*)bt;
    u64 sq = 0ull;
    #pragma unroll
    for (int cp = 0; cp < 5; ++cp) {
        ulonglong2 bb = btv[cp];
        u64 a0 = bb.x, a1 = bb.y;
        #pragma unroll
        for (int cc = 0; cc < 5; ++cc) {
            ulonglong2 w0 = Mv[(2*cp)   * 5 + cc];
            ulonglong2 w1 = Mv[(2*cp+1) * 5 + cc];
            a0 = fma2(xc[2*cc],   w0.x, a0);
            a0 = fma2(xc[2*cc+1], w0.y, a0);
            a1 = fma2(xc[2*cc],   w1.x, a1);
            a1 = fma2(xc[2*cc+1], w1.y, a1);
        }
        sq = fma2(a0, a0, sq);
        sq = fma2(a1, a1, sq);
    }
    return sq;
}

__global__ void __launch_bounds__(TPB, 3) kitnet_kernel(
    const float* __restrict__ x,
    const float* __restrict__ Wt,
    const float* __restrict__ hbt,
    const float* __restrict__ vbt,
    const float* __restrict__ Wh,
    const float* __restrict__ hbh,
    const float* __restrict__ vbh,
    const int*   __restrict__ clusters,
    float* __restrict__ out,
    int B)
{
    extern __shared__ char smem[];
    u64* xb0   = (u64*)(smem + OFF_X0);
    u64* xb1   = (u64*)(smem + OFF_X1);
    u64* MT    = (u64*)(smem + OFF_MT);
    u64* BT    = (u64*)(smem + OFF_BT);
    u64* MH    = (u64*)(smem + OFF_MH);
    u64* BH    = (u64*)(smem + OFF_BH);
    int* perm  = (int*)(smem + OFF_PERM);
    int* tbase = (int*)(smem + OFF_TBASE);

    const int tid   = threadIdx.x;
    const int base  = blockIdx.x * RPB;
    const int nrows = min(RPB, B - base);
    const float* xg = x + (size_t)base * FDIM;

    // ---- prologue P1: raw weights -> scratch (inside X1 region), perm, stage tile 0 ----
    float* scr = (float*)(smem + OFF_X1);
    float* sW   = scr;          // [10][7][10]
    float* sHB  = scr + 700;    // [10][7]
    float* sVB  = scr + 770;    // [10][10]
    float* sWH  = scr + 870;    // [7][10]
    float* sHBH = scr + 940;    // [7]
    float* sVBH = scr + 947;    // [10]
    for (int i = tid; i < 700; i += TPB) sW[i]  = Wt[i];
    for (int i = tid; i < 70;  i += TPB) sHB[i] = hbt[i];
    for (int i = tid; i < 100; i += TPB) sVB[i] = vbt[i];
    for (int i = tid; i < 70;  i += TPB) sWH[i] = Wh[i];
    if (tid < HDIM)   sHBH[tid] = hbh[tid];
    if (tid < NTILES) sVBH[tid] = vbh[tid];
    for (int i = tid; i < FDIM; i += TPB) perm[i] = clusters[i];
    // stage tile 0 into X0 via global clusters (generic path)
    {
        const int npairs = min(nrows, 256);
        const int ntot = npairs * 10;
        for (int i = tid; i < ntot; i += TPB) {
            unsigned p = (unsigned)i / 10u;
            unsigned j = (unsigned)i - p * 10u;
            unsigned col = (unsigned)clusters[j];
            float v0 = xg[p * FDIM + col];
            float v1 = 0.0f;
            if ((int)p + 256 < nrows) v1 = xg[(p + 256u) * FDIM + col];
            xb0[p * XSTR + j] = pack2(v0, v1);
        }
    }
    __syncthreads();

    // ---- prologue P2: fold matrices ----
    for (int i = tid; i < NTILES * CDIM * CDIM; i += TPB) {
        int t  = i / 100;
        int r  = i - t * 100;
        int co = r / 10;
        int ci = r - co * 10;
        float m = (ci == co) ? -1.0f : 0.0f;
        #pragma unroll
        for (int h = 0; h < HDIM; ++h)
            m += sW[t * 70 + h * 10 + ci] * sW[t * 70 + h * 10 + co];
        ((float2*)MT)[i] = make_float2(m, m);
    }
    for (int i = tid; i < NTILES * CDIM; i += TPB) {
        int t = i / 10, c = i - t * 10;
        float b = sVB[i];
        #pragma unroll
        for (int h = 0; h < HDIM; ++h)
            b += sHB[t * HDIM + h] * sW[t * 70 + h * 10 + c];
        ((float2*)BT)[i] = make_float2(b, b);
    }
    for (int i = tid; i < CDIM * CDIM; i += TPB) {
        int j = i / 10, ii = i - j * 10;
        float m = 0.0f;
        #pragma unroll
        for (int h = 0; h < HDIM; ++h)
            m += sWH[h * 10 + ii] * sWH[h * 10 + j];
        ((float2*)MH)[i] = make_float2(m, m);
    }
    if (tid < NTILES) {
        float b = sVBH[tid];
        #pragma unroll
        for (int h = 0; h < HDIM; ++h)
            b += sHBH[h] * sWH[h * 10 + tid];
        ((float2*)BH)[tid] = make_float2(b, b);
    }
    if (tid < NTILES) {                 // contiguity fast-path (base must be even)
        const int* pp = perm + tid * 10;
        int b0 = pp[0];
        bool ok = ((b0 & 1) == 0);
        #pragma unroll
        for (int j = 1; j < 10; ++j) ok = ok && (pp[j] == b0 + j);
        tbase[tid] = ok ? b0 : -1;
    }
    __syncthreads();

    // ---- main loop: stage t+1 (other buffer) overlapped with compute t ----
    const u64* xr0 = xb0 + (unsigned)tid * XSTR;
    const u64* xr1 = xb1 + (unsigned)tid * XSTR;
    u64 tails[NTILES];

    #pragma unroll 1
    for (int t = 0; t < NTILES; ++t) {
        if (t < NTILES - 1)
            stage_tile(xg, (t & 1) ? xb0 : xb1, perm + (t + 1) * 10,
                       tbase[t + 1], nrows, tid);
        u64 sq = compute_tile((t & 1) ? xr1 : xr0, MT + t * 100, BT + t * 10);
        float e0, e1;
        unpack2(sq, e0, e1);
        tails[t] = pack2(0.5f * __logf(e0 * 0.1f), 0.5f * __logf(e1 * 0.1f));
        __syncthreads();
    }

    // ---- head: head_out = tails @ MH^T + b_h ----
    u64 ho[NTILES];
    {
        const ulonglong2* MHv = (const ulonglong2*)MH;
        const ulonglong2* BHv = (const ulonglong2*)BH;
        #pragma unroll
        for (int jp = 0; jp < 5; ++jp) {
            ulonglong2 bb = BHv[jp];
            u64 a0 = bb.x, a1 = bb.y;
            #pragma unroll
            for (int tt = 0; tt < 5; ++tt) {
                ulonglong2 w0 = MHv[(2*jp)   * 5 + tt];
                ulonglong2 w1 = MHv[(2*jp+1) * 5 + tt];
                a0 = fma2(tails[2*tt],   w0.x, a0);
                a0 = fma2(tails[2*tt+1], w0.y, a0);
                a1 = fma2(tails[2*tt],   w1.x, a1);
                a1 = fma2(tails[2*tt+1], w1.y, a1);
            }
            ho[2*jp]   = a0;
            ho[2*jp+1] = a1;
        }
    }

    // ---- restage outputs through smem (contiguous regions) for coalesced stores ----
    float* shh = (float*)smem;                    // [512][10] head, 20480 B
    float* sht = (float*)(smem + 20480);          // [512][10] tails
    {
        const bool v0 = (tid < nrows);
        const bool v1 = (tid + TPB < nrows);
        float2* h0 = (float2*)(shh + tid * 10);
        float2* h1 = (float2*)(shh + (tid + TPB) * 10);
        float2* t0 = (float2*)(sht + tid * 10);
        float2* t1 = (float2*)(sht + (tid + TPB) * 10);
        #pragma unroll
        for (int n = 0; n < 5; ++n) {
            float a0, b0, a1, b1, ta0, tb0, ta1, tb1;
            unpack2(ho[2*n],      a0, b0);
            unpack2(ho[2*n+1],    a1, b1);
            unpack2(tails[2*n],   ta0, tb0);
            unpack2(tails[2*n+1], ta1, tb1);
            if (v0) { h0[n] = make_float2(a0, a1); t0[n] = make_float2(ta0, ta1); }
            if (v1) { h1[n] = make_float2(b0, b1); t1[n] = make_float2(tb0, tb1); }
        }
    }
    __syncthreads();
    {
        const size_t toff = (size_t)B * NTILES;
        float2* oh = (float2*)(out + (size_t)base * NTILES);
        float2* ot = (float2*)(out + toff + (size_t)base * NTILES);
        const float2* s2h = (const float2*)shh;
        const float2* s2t = (const float2*)sht;
        const int n2 = (nrows * NTILES) >> 1;     // nrows*10 always even
        #pragma unroll 4
        for (int i = tid; i < n2; i += TPB) {
            oh[i] = s2h[i];
            ot[i] = s2t[i];
        }
    }
}

extern "C" void kernel_launch(void* const* d_in, const int* in_sizes, int n_in,
                              void* d_out, int out_size)
{
    const float* x   = (const float*)d_in[0];
    const float* Wt  = (const float*)d_in[1];
    const float* hbt = (const float*)d_in[2];
    const float* vbt = (const float*)d_in[3];
    const float* Wh  = (const float*)d_in[4];
    const float* hbh = (const float*)d_in[5];
    const float* vbh = (const float*)d_in[6];
    const int*   cls = (const int*)d_in[7];

    const int B = in_sizes[0] / FDIM;
    const int grid = (B + RPB - 1) / RPB;

    cudaFuncSetAttribute(kitnet_kernel, cudaFuncAttributeMaxDynamicSharedMemorySize, SMEM_BYTES);
    kitnet_kernel<<<grid, TPB, SMEM_BYTES>>>(x, Wt, hbt, vbt, Wh, hbh, vbh, cls,
                                             (float*)d_out, B);
}

// round 5
// speedup vs baseline: 1.3376x; 1.3376x over previous
#include <cuda_runtime.h>
#include <cstddef>

// KitNET_5257039970983 — R5: warp-local staging, zero block barriers in main loop,
// register software pipeline (LDG t+1 || compute t). Folded M = W^T W - I compute.
// Inputs: x(B,100) f32, Wt(10,7,10), hbias_t(10,7), vbias_t(10,10),
//         Wh(7,10), hbias_h(7), vbias_h(10), clusters(10,10) i32
// Output: head_out(B,10) then tails(B,10), fp32.

#define NTILES 10
#define CDIM   10
#define HDIM   7
#define FDIM   100
#define TPB    256
#define RPB    512
#define PSTR   11                 // u64 per pair-row in warp slice (88B, conflict-free LDS.64)
#define SLICE_U64 (32*PSTR)       // 352 u64 = 2816 B per warp

// ---- smem layout (byte offsets) ----
#define OFF_XS    0               // 8 * 2816 = 22528
#define OFF_MT    22528           // u64[10][10][10] = 8000
#define OFF_BT    30528           // u64[10][10] = 800
#define OFF_MH    31328           // u64[10][10] = 800
#define OFF_BH    32128           // u64[10] = 80
#define OFF_PERM  32208           // int[100] = 400
#define OFF_TBASE 32608           // int[10] = 40
#define SMEM_BYTES 32656

typedef unsigned long long u64;

__device__ __forceinline__ u64 fma2(u64 a, u64 b, u64 c) {
    u64 d;
    asm("fma.rn.f32x2 %0, %1, %2, %3;" : "=l"(d) : "l"(a), "l"(b), "l"(c));
    return d;
}
__device__ __forceinline__ u64 pack2(float x, float y) {
    u64 d;
    asm("mov.b64 %0, {%1, %2};" : "=l"(d) : "f"(x), "f"(y));
    return d;
}
__device__ __forceinline__ void unpack2(u64 a, float& x, float& y) {
    asm("mov.b64 {%0, %1}, %2;" : "=f"(x), "=f"(y) : "l"(a));
}

// ---- warp-local staging: load one tile's 10 cols for this warp's 32 pairs ----
// fast path (tb>=0): 10 items/lane, each LDG.64 ; generic: 20 items/lane LDG.32
__device__ __forceinline__ void stage_load(const float* __restrict__ x, float rv[20],
                                           const int* __restrict__ pp, int tb,
                                           int rowbase, int B, int lane)
{
    if (tb >= 0) {
        #pragma unroll
        for (int i = 0; i < 10; ++i) {
            int id = 32*i + lane;                  // 0..319
            int p  = id / 10;
            int rem = id - 10*p;
            int h  = rem / 5;
            int k  = rem - 5*h;
            int row = rowbase + p + h*256;
            float2 v = make_float2(0.0f, 0.0f);
            if (row < B) v = *(const float2*)(x + (size_t)row*FDIM + tb + 2*k);
            rv[2*i]   = v.x;
            rv[2*i+1] = v.y;
        }
    } else {
        #pragma unroll
        for (int i = 0; i < 20; ++i) {
            int id = 32*i + lane;                  // 0..639
            int p  = id / 20;
            int rem = id - 20*p;
            int h  = rem / 10;
            int j  = rem - 10*h;
            int row = rowbase + p + h*256;
            float v = 0.0f;
            if (row < B) v = x[(size_t)row*FDIM + pp[j]];
            rv[i] = v;
        }
    }
}

__device__ __forceinline__ void stage_store(float* __restrict__ slf, const float rv[20],
                                            int tb, int lane)
{
    if (tb >= 0) {
        #pragma unroll
        for (int i = 0; i < 10; ++i) {
            int id = 32*i + lane;
            int p  = id / 10;
            int rem = id - 10*p;
            int h  = rem / 5;
            int k  = rem - 5*h;
            slf[p*22 + 4*k + h]     = rv[2*i];
            slf[p*22 + 4*k + 2 + h] = rv[2*i+1];
        }
    } else {
        #pragma unroll
        for (int i = 0; i < 20; ++i) {
            int id = 32*i + lane;
            int p  = id / 20;
            int rem = id - 20*p;
            int h  = rem / 10;
            int j  = rem - 10*h;
            slf[p*22 + 2*j + h] = rv[i];
        }
    }
}

// err = xc @ M_t + b_t ; packed sum of squares
__device__ __forceinline__ u64 compute_tile(const u64 xc[CDIM],
                                            const u64* __restrict__ Mt,
                                            const u64* __restrict__ bt)
{
    const ulonglong2* Mv  = (const ulonglong2*)Mt;
    const ulonglong2* btv = (const ulonglong2*)bt;
    u64 sq = 0ull;
    #pragma unroll
    for (int cp = 0; cp < 5; ++cp) {
        ulonglong2 bb = btv[cp];
        u64 a0 = bb.x, a1 = bb.y;
        #pragma unroll
        for (int cc = 0; cc < 5; ++cc) {
            ulonglong2 w0 = Mv[(2*cp)   * 5 + cc];
            ulonglong2 w1 = Mv[(2*cp+1) * 5 + cc];
            a0 = fma2(xc[2*cc],   w0.x, a0);
            a0 = fma2(xc[2*cc+1], w0.y, a0);
            a1 = fma2(xc[2*cc],   w1.x, a1);
            a1 = fma2(xc[2*cc+1], w1.y, a1);
        }
        sq = fma2(a0, a0, sq);
        sq = fma2(a1, a1, sq);
    }
    return sq;
}

__global__ void __launch_bounds__(TPB, 3) kitnet_kernel(
    const float* __restrict__ x,
    const float* __restrict__ Wt,
    const float* __restrict__ hbt,
    const float* __restrict__ vbt,
    const float* __restrict__ Wh,
    const float* __restrict__ hbh,
    const float* __restrict__ vbh,
    const int*   __restrict__ clusters,
    float* __restrict__ out,
    int B)
{
    extern __shared__ char smem[];
    u64* xs    = (u64*)(smem + OFF_XS);
    u64* MT    = (u64*)(smem + OFF_MT);
    u64* BT    = (u64*)(smem + OFF_BT);
    u64* MH    = (u64*)(smem + OFF_MH);
    u64* BH    = (u64*)(smem + OFF_BH);
    int* perm  = (int*)(smem + OFF_PERM);
    int* tbase = (int*)(smem + OFF_TBASE);

    const int tid  = threadIdx.x;
    const int lane = tid & 31;
    const int wid  = tid >> 5;
    const int base = blockIdx.x * RPB;

    // ---- prologue P1: raw weights -> scratch (inside XS region), perm ----
    float* scr = (float*)xs;
    float* sW   = scr;          // [10][7][10]
    float* sHB  = scr + 700;
    float* sVB  = scr + 770;
    float* sWH  = scr + 870;
    float* sHBH = scr + 940;
    float* sVBH = scr + 947;
    for (int i = tid; i < 700; i += TPB) sW[i]  = Wt[i];
    for (int i = tid; i < 70;  i += TPB) sHB[i] = hbt[i];
    for (int i = tid; i < 100; i += TPB) sVB[i] = vbt[i];
    for (int i = tid; i < 70;  i += TPB) sWH[i] = Wh[i];
    if (tid < HDIM)   sHBH[tid] = hbh[tid];
    if (tid < NTILES) sVBH[tid] = vbh[tid];
    for (int i = tid; i < FDIM; i += TPB) perm[i] = clusters[i];
    __syncthreads();

    // ---- prologue P2: fold matrices; contiguity fast-path detection ----
    for (int i = tid; i < NTILES * CDIM * CDIM; i += TPB) {
        int t  = i / 100;
        int r  = i - t * 100;
        int co = r / 10;
        int ci = r - co * 10;
        float m = (ci == co) ? -1.0f : 0.0f;
        #pragma unroll
        for (int h = 0; h < HDIM; ++h)
            m += sW[t * 70 + h * 10 + ci] * sW[t * 70 + h * 10 + co];
        ((float2*)MT)[i] = make_float2(m, m);
    }
    for (int i = tid; i < NTILES * CDIM; i += TPB) {
        int t = i / 10, c = i - t * 10;
        float b = sVB[i];
        #pragma unroll
        for (int h = 0; h < HDIM; ++h)
            b += sHB[t * HDIM + h] * sW[t * 70 + h * 10 + c];
        ((float2*)BT)[i] = make_float2(b, b);
    }
    for (int i = tid; i < CDIM * CDIM; i += TPB) {
        int j = i / 10, ii = i - j * 10;
        float m = 0.0f;
        #pragma unroll
        for (int h = 0; h < HDIM; ++h)
            m += sWH[h * 10 + ii] * sWH[h * 10 + j];
        ((float2*)MH)[i] = make_float2(m, m);
    }
    if (tid < NTILES) {
        float b = sVBH[tid];
        #pragma unroll
        for (int h = 0; h < HDIM; ++h)
            b += sHBH[h] * sWH[h * 10 + tid];
        ((float2*)BH)[tid] = make_float2(b, b);
    }
    if (tid < NTILES) {
        const int* pp = perm + tid * 10;
        int b0 = pp[0];
        bool ok = ((b0 & 1) == 0);
        #pragma unroll
        for (int j = 1; j < 10; ++j) ok = ok && (pp[j] == b0 + j);
        tbase[tid] = ok ? b0 : -1;
    }
    __syncthreads();
    // ======== no block barriers beyond this point ========

    const int rowbase = base + wid * 32;
    u64*   xsw = xs + wid * SLICE_U64;
    float* slf = (float*)xsw;

    float rv[20];
    u64 tails[NTILES];

    // stage tile 0
    stage_load(x, rv, perm, tbase[0], rowbase, B, lane);
    stage_store(slf, rv, tbase[0], lane);
    __syncwarp();

    #pragma unroll 1
    for (int t = 0; t < NTILES; ++t) {
        if (t < NTILES - 1)
            stage_load(x, rv, perm + (t + 1) * 10, tbase[t + 1], rowbase, B, lane);

        u64 xc[CDIM];
        #pragma unroll
        for (int j = 0; j < CDIM; ++j) xc[j] = xsw[lane * PSTR + j];

        u64 sq = compute_tile(xc, MT + t * 100, BT + t * 10);
        float e0, e1;
        unpack2(sq, e0, e1);
        tails[t] = pack2(0.5f * __logf(e0 * 0.1f), 0.5f * __logf(e1 * 0.1f));

        __syncwarp();                         // all lanes done reading slice
        if (t < NTILES - 1)
            stage_store(slf, rv, tbase[t + 1], lane);
        __syncwarp();                         // writes visible for next xc load
    }

    // ---- head: head_out = tails @ MH^T + b_h ----
    u64 ho[NTILES];
    {
        const ulonglong2* MHv = (const ulonglong2*)MH;
        const ulonglong2* BHv = (const ulonglong2*)BH;
        #pragma unroll
        for (int jp = 0; jp < 5; ++jp) {
            ulonglong2 bb = BHv[jp];
            u64 a0 = bb.x, a1 = bb.y;
            #pragma unroll
            for (int tt = 0; tt < 5; ++tt) {
                ulonglong2 w0 = MHv[(2*jp)   * 5 + tt];
                ulonglong2 w1 = MHv[(2*jp+1) * 5 + tt];
                a0 = fma2(tails[2*tt],   w0.x, a0);
                a0 = fma2(tails[2*tt+1], w0.y, a0);
                a1 = fma2(tails[2*tt],   w1.x, a1);
                a1 = fma2(tails[2*tt+1], w1.y, a1);
            }
            ho[2*jp]   = a0;
            ho[2*jp+1] = a1;
        }
    }

    // ---- warp-local output restage: round 0 = head, round 1 = tails ----
    const long long B10 = (long long)B * NTILES;
    #pragma unroll 1
    for (int r = 0; r < 2; ++r) {
        const u64* src = r ? tails : ho;
        #pragma unroll
        for (int n = 0; n < NTILES; ++n) {
            float a, b;
            unpack2(src[n], a, b);
            slf[lane * 10 + n]       = a;
            slf[320 + lane * 10 + n] = b;
        }
        __syncwarp();
        const long long bound = (long long)(r + 1) * B10;
        #pragma unroll
        for (int i = 0; i < 5; ++i) {
            int q  = lane + 32 * i;           // 0..159
            int h  = (q >= 80) ? 1 : 0;
            int qq = q - 80 * h;
            long long off = (long long)r * B10
                          + (long long)(rowbase + h * 256) * 10 + 4 * qq;
            float4 v = *(const float4*)(slf + h * 320 + 4 * qq);
            if (off + 4 <= bound && ((off & 3) == 0)) {
                *(float4*)(out + off) = v;
            } else {
                const float* vf = (const float*)&v;
                #pragma unroll
                for (int kk = 0; kk < 4; ++kk)
                    if (off + kk < bound) out[off + kk] = vf[kk];
            }
        }
        __syncwarp();
    }
}

extern "C" void kernel_launch(void* const* d_in, const int* in_sizes, int n_in,
                              void* d_out, int out_size)
{
    const float* x   = (const float*)d_in[0];
    const float* Wt  = (const float*)d_in[1];
    const float* hbt = (const float*)d_in[2];
    const float* vbt = (const float*)d_in[3];
    const float* Wh  = (const float*)d_in[4];
    const float* hbh = (const float*)d_in[5];
    const float* vbh = (const float*)d_in[6];
    const int*   cls = (const int*)d_in[7];

    const int B = in_sizes[0] / FDIM;
    const int grid = (B + RPB - 1) / RPB;

    cudaFuncSetAttribute(kitnet_kernel, cudaFuncAttributeMaxDynamicSharedMemorySize, SMEM_BYTES);
    kitnet_kernel<<<grid, TPB, SMEM_BYTES>>>(x, Wt, hbt, vbt, Wh, hbh, vbh, cls,
                                             (float*)d_out, B);
}